// round 4
// baseline (speedup 1.0000x reference)
#include <cuda_runtime.h>
#include <cuda_bf16.h>
#include <cstdint>

#define B_    4
#define C_    64
#define T_    80
#define H_    36
#define W_    64
#define S_    2304
#define N_    128
#define NT_   10
#define TOUT_ 71
#define F_    320
#define KC    64            // K elements per chunk
#define NCHUNK (S_/KC)      // 36

// ---------------- device scratch -------------------------------------------
__device__ float g_gx[W_*N_];
__device__ float g_gy[H_*N_];
__device__ float g_invZ[N_];
__device__ __align__(16) __nv_bfloat16 g_wsT[N_*S_];   // B matrix: [n][s] bf16
__device__ float g_Rt[B_*N_*T_];                        // [b][n][t]

// ---------------- helpers ---------------------------------------------------
__device__ __forceinline__ uint32_t smem_u32(const void* p) {
    uint32_t a;
    asm("{ .reg .u64 t; cvta.to.shared.u64 t, %1; cvt.u32.u64 %0, t; }" : "=r"(a) : "l"(p));
    return a;
}
__device__ __forceinline__ uint32_t pack_bf16(float lo, float hi) {
    uint32_t r;
    asm("cvt.rn.bf16x2.f32 %0, %1, %2;" : "=r"(r) : "f"(hi), "f"(lo));
    return r;
}
__device__ __forceinline__ void cp16(uint32_t dst, const void* src) {
    asm volatile("cp.async.cg.shared.global [%0], [%1], 16;" :: "r"(dst), "l"(src) : "memory");
}
#define CP_COMMIT() asm volatile("cp.async.commit_group;" ::: "memory")
#define CP_WAIT1()  asm volatile("cp.async.wait_group 1;" ::: "memory")

__device__ __forceinline__ void mma_bf16(float* d, const uint32_t* a, const uint32_t* b) {
    asm volatile("mma.sync.aligned.m16n8k16.row.col.f32.bf16.bf16.f32 "
        "{%0,%1,%2,%3}, {%4,%5,%6,%7}, {%8,%9}, {%0,%1,%2,%3};"
        : "+f"(d[0]), "+f"(d[1]), "+f"(d[2]), "+f"(d[3])
        : "r"(a[0]), "r"(a[1]), "r"(a[2]), "r"(a[3]), "r"(b[0]), "r"(b[1]));
}
__device__ __forceinline__ void ldmx4(uint32_t* r, uint32_t addr) {
    asm volatile("ldmatrix.sync.aligned.m8n8.x4.shared.b16 {%0,%1,%2,%3}, [%4];"
        : "=r"(r[0]), "=r"(r[1]), "=r"(r[2]), "=r"(r[3]) : "r"(addr));
}

// bf16 tile, 128B rows (64 k elems), 16B granules g=0..7, XOR swizzle
__device__ __forceinline__ uint32_t swz(int row, int g) {
    return (uint32_t)(row * 128 + (((g ^ (row & 7)) & 7) << 4));
}

// ---------------------------------------------------------------------------
// 1) Gaussian factors
// ---------------------------------------------------------------------------
__global__ void setup_kernel(const float* __restrict__ wx, const float* __restrict__ wy,
                             const float* __restrict__ wsx, const float* __restrict__ wsy) {
    int n = threadIdx.x;
    float rx = fmaxf(wsx[n], 0.0f), ry = fmaxf(wsy[n], 0.0f);
    float inv2sx = 1.0f / (2.0f * (0.1f + rx * rx));
    float inv2sy = 1.0f / (2.0f * (0.1f + ry * ry));
    float cx = wx[n], cy = wy[n];
    float sgx = 0.0f;
    for (int xp = 0; xp < W_; xp++) {
        float xv = ((float)xp - 0.5f * W_ + 0.5f) / (float)W_;
        float d = xv - cx; float g = expf(-d * d * inv2sx);
        g_gx[xp * N_ + n] = g; sgx += g;
    }
    float sgy = 0.0f;
    for (int yp = 0; yp < H_; yp++) {
        float yv = ((float)yp - 0.5f * H_ + 0.5f) / (float)H_;
        float d = yv - cy; float g = expf(-d * d * inv2sy);
        g_gy[yp * N_ + n] = g; sgy += g;
    }
    g_invZ[n] = 1.0f / (0.1f + sgx * sgy);
}

// ---------------------------------------------------------------------------
// 2) wsT[n][s] bf16
// ---------------------------------------------------------------------------
__global__ void wsfill_kernel() {
    int idx = blockIdx.x * blockDim.x + threadIdx.x;
    if (idx >= N_ * S_) return;
    int n = idx / S_;
    int s = idx - n * S_;
    int yp = s / W_;
    int xp = s - yp * W_;
    float v = g_gy[yp * N_ + n] * g_gx[xp * N_ + n] * g_invZ[n];
    g_wsT[idx] = __float2bfloat16(v);
}

// ---------------------------------------------------------------------------
// 3) HMMA GEMM: 128 rows=(f,c) x 128 n x K=2304 per CTA, 160 CTAs.
//    A and B both bf16 in swizzled SMEM; ldmatrix.x4 fragment loads.
// ---------------------------------------------------------------------------
#define SM_A0   0
#define SM_A1   16384
#define SM_B0   32768
#define SM_B1   49152
#define SMEM_SZ 69632          // epilogue T1[128][136] fp32 = 69632 B
#define T1_STRIDE 136

extern "C" __global__ void __launch_bounds__(256)
gemm_kernel(const float* __restrict__ x, const float* __restrict__ wc) {
    extern __shared__ __align__(16) char smem[];
    const uint32_t sb = smem_u32(smem);
    const int tid  = threadIdx.x;
    const int wid  = tid >> 5;
    const int lane = tid & 31;
    const int wm   = wid & 3;     // rows wm*32..+31
    const int wn   = wid >> 2;    // cols wn*64..+63

    // loader mapping: row lr = tid/2, half lh = tid&1 (32 k-elems each)
    const int lr = tid >> 1;
    const int lh = tid & 1;
    const int gr = blockIdx.x * 128 + lr;
    const int lf = gr >> 6;
    const int lc = gr & 63;
    const int lbb = lf / T_;
    const int ltt = lf - lbb * T_;
    const float* asrc = x + ((size_t)((lbb * C_ + lc) * T_ + ltt)) * S_ + lh * 32;
    const __nv_bfloat16* bsrc = g_wsT + (size_t)lr * S_ + lh * 32;

    const uint32_t abuf[2] = { sb + SM_A0, sb + SM_A1 };
    const uint32_t bbuf[2] = { sb + SM_B0, sb + SM_B1 };

    auto issueB = [&](int chunk, int p) {
#pragma unroll
        for (int j = 0; j < 4; j++) {
            int g = lh * 4 + j;
            cp16(bbuf[p] + swz(lr, g), bsrc + (size_t)chunk * KC + (g - lh * 4) * 8);
        }
    };
    // A: LDG fp32 (8 x float4), pack bf16, STS (4 x 16B)
    float4 fa[8];
    auto ldA = [&](int chunk) {
        const float4* ap = (const float4*)(asrc + (size_t)chunk * KC);
#pragma unroll
        for (int q = 0; q < 8; q++) fa[q] = __ldg(ap + q);
    };
    auto stsA = [&](int p) {
#pragma unroll
        for (int j = 0; j < 4; j++) {
            uint4 v;
            v.x = pack_bf16(fa[2*j].x,   fa[2*j].y);
            v.y = pack_bf16(fa[2*j].z,   fa[2*j].w);
            v.z = pack_bf16(fa[2*j+1].x, fa[2*j+1].y);
            v.w = pack_bf16(fa[2*j+1].z, fa[2*j+1].w);
            uint32_t d = abuf[p] + swz(lr, lh * 4 + j);
            asm volatile("st.shared.v4.b32 [%0], {%1,%2,%3,%4};"
                :: "r"(d), "r"(v.x), "r"(v.y), "r"(v.z), "r"(v.w) : "memory");
        }
    };

    float acc[2][8][4];
#pragma unroll
    for (int mt = 0; mt < 2; mt++)
#pragma unroll
        for (int j = 0; j < 8; j++)
#pragma unroll
            for (int q = 0; q < 4; q++) acc[mt][j][q] = 0.0f;

    // ldmatrix lane-address components
    const int arow0 = wm * 32 + (lane & 15);          // + mt*16
    const int agb   = lane >> 4;                       // 0..1 (k half)
    const int nrow0 = wn * 64 + ((lane >> 4) << 3) + (lane & 7);  // + jp*16
    const int bgb   = (lane >> 3) & 1;                 // 0..1 (k half)

    issueB(0, 0); CP_COMMIT();
    issueB(1, 1); CP_COMMIT();
    ldA(0);

    for (int i = 0; i < NCHUNK; i++) {
        const int p = i & 1;
        stsA(p);
        CP_WAIT1();
        __syncthreads();
        if (i + 1 < NCHUNK) ldA(i + 1);

        const uint32_t Ab = abuf[p], Bb = bbuf[p];
#pragma unroll
        for (int q = 0; q < 4; q++) {
            uint32_t afr[2][4];
#pragma unroll
            for (int mt = 0; mt < 2; mt++)
                ldmx4(afr[mt], Ab + swz(arow0 + mt * 16, q * 2 + agb));
            uint32_t bfr[4][4];
#pragma unroll
            for (int jp = 0; jp < 4; jp++)
                ldmx4(bfr[jp], Bb + swz(nrow0 + jp * 16, q * 2 + bgb));
#pragma unroll
            for (int mt = 0; mt < 2; mt++)
#pragma unroll
                for (int jp = 0; jp < 4; jp++) {
                    mma_bf16(acc[mt][jp * 2],     afr[mt], &bfr[jp][0]);
                    mma_bf16(acc[mt][jp * 2 + 1], afr[mt], &bfr[jp][2]);
                }
        }
        __syncthreads();
        if (i + 2 < NCHUNK) issueB(i + 2, p);
        CP_COMMIT();
    }

    // ---- epilogue: T1 -> SMEM, fold wc, reduce over c ----
    float* Tsm = (float*)smem;      // [128][T1_STRIDE]
    const int lrow = lane >> 2;
    const int lq   = lane & 3;
#pragma unroll
    for (int mt = 0; mt < 2; mt++) {
#pragma unroll
        for (int j = 0; j < 8; j++) {
            int r0  = wm * 32 + mt * 16 + lrow;
            int col = wn * 64 + j * 8 + lq * 2;
            uint32_t a0 = sb + (uint32_t)((r0 * T1_STRIDE + col) * 4);
            uint32_t a1 = sb + (uint32_t)(((r0 + 8) * T1_STRIDE + col) * 4);
            asm volatile("st.shared.v2.f32 [%0], {%1,%2};"
                         :: "r"(a0), "f"(acc[mt][j][0]), "f"(acc[mt][j][1]));
            asm volatile("st.shared.v2.f32 [%0], {%1,%2};"
                         :: "r"(a1), "f"(acc[mt][j][2]), "f"(acc[mt][j][3]));
        }
    }
    __syncthreads();
    {
        int fl = tid >> 7;
        int n  = tid & 127;
        float s = 0.0f;
        const float* tp = Tsm + (size_t)fl * 64 * T1_STRIDE + n;
#pragma unroll 16
        for (int c2 = 0; c2 < 64; c2++)
            s += tp[c2 * T1_STRIDE] * __ldg(&wc[c2 * N_ + n]);
        int fg = blockIdx.x * 2 + fl;
        int b2 = fg / T_, t2 = fg - (fg / T_) * T_;
        g_Rt[(b2 * N_ + n) * T_ + t2] = s;
    }
}

// ---------------------------------------------------------------------------
// 4) temporal conv: one warp per (b, n) row
// ---------------------------------------------------------------------------
__global__ void conv_kernel(const float* __restrict__ wt, const float* __restrict__ wb,
                            float* __restrict__ out) {
    __shared__ float rr[8][80];
    __shared__ float wts[8][10];
    int wid = threadIdx.x >> 5, lane = threadIdx.x & 31;
    int row = blockIdx.x * 8 + wid;        // row = b*N + n
    int n = row & 127;
    const float* R = g_Rt + (size_t)row * T_;
    if (lane < 10) wts[wid][lane] = wt[lane * N_ + n];
    rr[wid][lane]      = R[lane];
    rr[wid][lane + 32] = R[lane + 32];
    if (lane < 16) rr[wid][lane + 64] = R[lane + 64];
    __syncwarp();
    float bias = wb[n];
    for (int t0 = lane; t0 < TOUT_; t0 += 32) {
        float s = bias;
#pragma unroll
        for (int k = 0; k < NT_; k++) s += rr[wid][t0 + k] * wts[wid][k];
        out[(size_t)row * TOUT_ + t0] = s;
    }
}

// ---------------------------------------------------------------------------
extern "C" void kernel_launch(void* const* d_in, const int* in_sizes, int n_in,
                              void* d_out, int out_size) {
    (void)in_sizes; (void)n_in; (void)out_size;
    const float* x   = (const float*)d_in[0];
    const float* wc  = (const float*)d_in[2];
    const float* wx  = (const float*)d_in[3];
    const float* wy  = (const float*)d_in[4];
    const float* wsx = (const float*)d_in[5];
    const float* wsy = (const float*)d_in[6];
    const float* wt  = (const float*)d_in[7];
    const float* wb  = (const float*)d_in[8];
    float* out = (float*)d_out;

    cudaFuncSetAttribute(gemm_kernel, cudaFuncAttributeMaxDynamicSharedMemorySize, SMEM_SZ);

    setup_kernel<<<1, N_>>>(wx, wy, wsx, wsy);
    wsfill_kernel<<<(N_ * S_ + 255) / 256, 256>>>();
    gemm_kernel<<<F_ / 2, 256, SMEM_SZ>>>(x, wc);
    conv_kernel<<<(B_ * N_) / 8, 256>>>(wt, wb, out);
}

// round 5
// speedup vs baseline: 1.1588x; 1.1588x over previous
#include <cuda_runtime.h>
#include <cuda_bf16.h>
#include <cstdint>

#define B_    4
#define C_    64
#define T_    80
#define H_    36
#define W_    64
#define S_    2304
#define N_    128
#define NT_   10
#define TOUT_ 71
#define F_    320
#define KC    64            // K elements per chunk
#define NCHUNK (S_/KC)      // 36

// ---------------- device scratch -------------------------------------------
__device__ float g_gx[W_*N_];
__device__ float g_gy[H_*N_];
__device__ float g_invZ[N_];
__device__ __align__(16) __nv_bfloat16 g_wsT[N_*S_];   // B matrix: [n][s] bf16
__device__ float g_Rt[B_*N_*T_];                        // [b][n][t]

// ---------------- helpers ---------------------------------------------------
__device__ __forceinline__ uint32_t smem_u32(const void* p) {
    uint32_t a;
    asm("{ .reg .u64 t; cvta.to.shared.u64 t, %1; cvt.u32.u64 %0, t; }" : "=r"(a) : "l"(p));
    return a;
}
__device__ __forceinline__ uint32_t pack_bf16(float lo, float hi) {
    uint32_t r;
    asm("cvt.rn.bf16x2.f32 %0, %1, %2;" : "=r"(r) : "f"(hi), "f"(lo));
    return r;
}
__device__ __forceinline__ void cp16(uint32_t dst, const void* src) {
    asm volatile("cp.async.cg.shared.global [%0], [%1], 16;" :: "r"(dst), "l"(src) : "memory");
}
#define CP_COMMIT() asm volatile("cp.async.commit_group;" ::: "memory")
#define CP_WAIT1()  asm volatile("cp.async.wait_group 1;" ::: "memory")

__device__ __forceinline__ void mma_bf16(float* d, const uint32_t* a, const uint32_t* b) {
    asm volatile("mma.sync.aligned.m16n8k16.row.col.f32.bf16.bf16.f32 "
        "{%0,%1,%2,%3}, {%4,%5,%6,%7}, {%8,%9}, {%0,%1,%2,%3};"
        : "+f"(d[0]), "+f"(d[1]), "+f"(d[2]), "+f"(d[3])
        : "r"(a[0]), "r"(a[1]), "r"(a[2]), "r"(a[3]), "r"(b[0]), "r"(b[1]));
}

// A tile: 64 rows x 256B (64 fp32). 8B-granule swizzle: e8' = e8 ^ ((r&3)<<2).
__device__ __forceinline__ uint32_t aswz8(int r, int e8) {
    return (uint32_t)(r * 256 + ((e8 ^ ((r & 3) << 2)) << 3));
}
// A cp.async (16B granule u = e8>>1): u' = u ^ ((r&3)<<1)
__device__ __forceinline__ uint32_t aswz16(int r, int u) {
    return (uint32_t)(r * 256 + ((u ^ ((r & 3) << 1)) << 4));
}
// B tile: 128 rows x 128B bf16, 16B granules, XOR swizzle (conflict-free, R3-proven)
__device__ __forceinline__ uint32_t bswz(int n, int g) {
    return (uint32_t)(n * 128 + (((g ^ (n & 7)) & 7) << 4));
}

// ---------------------------------------------------------------------------
// 1) Gaussian factors
// ---------------------------------------------------------------------------
__global__ void setup_kernel(const float* __restrict__ wx, const float* __restrict__ wy,
                             const float* __restrict__ wsx, const float* __restrict__ wsy) {
    int n = threadIdx.x;
    float rx = fmaxf(wsx[n], 0.0f), ry = fmaxf(wsy[n], 0.0f);
    float inv2sx = 1.0f / (2.0f * (0.1f + rx * rx));
    float inv2sy = 1.0f / (2.0f * (0.1f + ry * ry));
    float cx = wx[n], cy = wy[n];
    float sgx = 0.0f;
    for (int xp = 0; xp < W_; xp++) {
        float xv = ((float)xp - 0.5f * W_ + 0.5f) / (float)W_;
        float d = xv - cx; float g = expf(-d * d * inv2sx);
        g_gx[xp * N_ + n] = g; sgx += g;
    }
    float sgy = 0.0f;
    for (int yp = 0; yp < H_; yp++) {
        float yv = ((float)yp - 0.5f * H_ + 0.5f) / (float)H_;
        float d = yv - cy; float g = expf(-d * d * inv2sy);
        g_gy[yp * N_ + n] = g; sgy += g;
    }
    g_invZ[n] = 1.0f / (0.1f + sgx * sgy);
}

// ---------------------------------------------------------------------------
// 2) wsT[n][s] bf16
// ---------------------------------------------------------------------------
__global__ void wsfill_kernel() {
    int idx = blockIdx.x * blockDim.x + threadIdx.x;
    if (idx >= N_ * S_) return;
    int n = idx / S_;
    int s = idx - n * S_;
    int yp = s / W_;
    int xp = s - yp * W_;
    float v = g_gy[yp * N_ + n] * g_gx[xp * N_ + n] * g_invZ[n];
    g_wsT[idx] = __float2bfloat16(v);
}

// ---------------------------------------------------------------------------
// 3) HMMA GEMM: one frame per CTA. M=64 (channels) x N=128 x K=2304.
//    grid 320, 256 threads, 2 stages cp.async, 64KB SMEM -> 2 CTA/SM.
// ---------------------------------------------------------------------------
#define SM_A0   0
#define SM_A1   16384
#define SM_B0   32768
#define SM_B1   49152
#define SMEM_SZ 65536
#define T1_STRIDE 132

extern "C" __global__ void __launch_bounds__(256, 2)
gemm_kernel(const float* __restrict__ x, const float* __restrict__ wc) {
    extern __shared__ __align__(16) char smem[];
    const uint32_t sb = smem_u32(smem);
    const int tid  = threadIdx.x;
    const int wid  = tid >> 5;
    const int lane = tid & 31;
    const int wm   = wid & 1;     // rows wm*32..+31 (channels)
    const int wn   = wid >> 1;    // cols wn*32..+31 (targets)
    const int lrow = lane >> 2;   // 0..7
    const int lq   = lane & 3;    // 0..3

    const int f  = blockIdx.x;          // frame
    const int bb = f / T_;
    const int tt = f - bb * T_;

    // A loader: row la = tid&63 (channel), 4 x 16B granules u = (tid>>6)*4 + j
    const int la = tid & 63;
    const int ub = (tid >> 6) << 2;
    const float* asrc = x + ((size_t)((bb * C_ + la) * T_ + tt)) * S_ + ub * 4;
    // B loader: row lb = tid&127 (target), 4 granules g = (tid>>7)*4 + j
    const int lb = tid & 127;
    const int gb = (tid >> 7) << 2;
    const __nv_bfloat16* bsrc = g_wsT + (size_t)lb * S_ + gb * 8;

    const uint32_t abuf[2] = { sb + SM_A0, sb + SM_A1 };
    const uint32_t bbuf[2] = { sb + SM_B0, sb + SM_B1 };

    auto issue = [&](int chunk, int p) {
#pragma unroll
        for (int j = 0; j < 4; j++)
            cp16(abuf[p] + aswz16(la, ub + j), asrc + (size_t)chunk * KC + j * 4);
#pragma unroll
        for (int j = 0; j < 4; j++)
            cp16(bbuf[p] + bswz(lb, gb + j), bsrc + (size_t)chunk * KC + j * 8);
    };

    float acc[2][4][4];
#pragma unroll
    for (int mt = 0; mt < 2; mt++)
#pragma unroll
        for (int j = 0; j < 4; j++)
#pragma unroll
            for (int q = 0; q < 4; q++) acc[mt][j][q] = 0.0f;

    issue(0, 0); CP_COMMIT();
    issue(1, 1); CP_COMMIT();

    for (int i = 0; i < NCHUNK; i++) {
        const int p = i & 1;
        CP_WAIT1();
        __syncthreads();
        const uint32_t Ab = abuf[p], Bb = bbuf[p];
#pragma unroll
        for (int q = 0; q < 4; q++) {
            uint32_t afr[2][4];
#pragma unroll
            for (int mt = 0; mt < 2; mt++) {
#pragma unroll
                for (int half = 0; half < 2; half++) {
#pragma unroll
                    for (int dr = 0; dr < 2; dr++) {
                        int r  = wm * 32 + mt * 16 + lrow + dr * 8;
                        int e8 = q * 8 + half * 4 + lq;
                        float2 v;
                        asm volatile("ld.shared.v2.f32 {%0,%1}, [%2];"
                                     : "=f"(v.x), "=f"(v.y) : "r"(Ab + aswz8(r, e8)));
                        afr[mt][half * 2 + dr] = pack_bf16(v.x, v.y);
                    }
                }
            }
            uint32_t bfr[4][2];
#pragma unroll
            for (int j = 0; j < 4; j++) {
                int n = wn * 32 + j * 8 + lrow;
#pragma unroll
                for (int half = 0; half < 2; half++) {
                    asm volatile("ld.shared.b32 %0, [%1];"
                        : "=r"(bfr[j][half]) : "r"(Bb + bswz(n, q * 2 + half) + lq * 4));
                }
            }
#pragma unroll
            for (int mt = 0; mt < 2; mt++)
#pragma unroll
                for (int j = 0; j < 4; j++)
                    mma_bf16(acc[mt][j], afr[mt], bfr[j]);
        }
        __syncthreads();
        if (i + 2 < NCHUNK) issue(i + 2, p);
        CP_COMMIT();
    }

    // ---- epilogue: T1[64 c][128 n] -> SMEM, fold wc, reduce over c ----
    float* Tsm = (float*)smem;      // [64][T1_STRIDE]
#pragma unroll
    for (int mt = 0; mt < 2; mt++) {
#pragma unroll
        for (int j = 0; j < 4; j++) {
            int r0  = wm * 32 + mt * 16 + lrow;
            int col = wn * 32 + j * 8 + lq * 2;
            uint32_t a0 = sb + (uint32_t)((r0 * T1_STRIDE + col) * 4);
            uint32_t a1 = sb + (uint32_t)(((r0 + 8) * T1_STRIDE + col) * 4);
            asm volatile("st.shared.v2.f32 [%0], {%1,%2};"
                         :: "r"(a0), "f"(acc[mt][j][0]), "f"(acc[mt][j][1]));
            asm volatile("st.shared.v2.f32 [%0], {%1,%2};"
                         :: "r"(a1), "f"(acc[mt][j][2]), "f"(acc[mt][j][3]));
        }
    }
    __syncthreads();
    {
        float* red = (float*)(smem + 64 * T1_STRIDE * 4);   // 256 floats
        int n = tid & 127;
        int h = tid >> 7;
        float s = 0.0f;
#pragma unroll 8
        for (int cc = 0; cc < 32; cc++) {
            int c2 = h * 32 + cc;
            s += Tsm[c2 * T1_STRIDE + n] * __ldg(&wc[c2 * N_ + n]);
        }
        red[h * 128 + n] = s;
        __syncthreads();
        if (h == 0)
            g_Rt[(bb * N_ + n) * T_ + tt] = red[n] + red[128 + n];
    }
}

// ---------------------------------------------------------------------------
// 4) temporal conv: one warp per (b, n) row
// ---------------------------------------------------------------------------
__global__ void conv_kernel(const float* __restrict__ wt, const float* __restrict__ wb,
                            float* __restrict__ out) {
    __shared__ float rr[8][80];
    __shared__ float wts[8][10];
    int wid = threadIdx.x >> 5, lane = threadIdx.x & 31;
    int row = blockIdx.x * 8 + wid;        // row = b*N + n
    int n = row & 127;
    const float* R = g_Rt + (size_t)row * T_;
    if (lane < 10) wts[wid][lane] = wt[lane * N_ + n];
    rr[wid][lane]      = R[lane];
    rr[wid][lane + 32] = R[lane + 32];
    if (lane < 16) rr[wid][lane + 64] = R[lane + 64];
    __syncwarp();
    float bias = wb[n];
    for (int t0 = lane; t0 < TOUT_; t0 += 32) {
        float s = bias;
#pragma unroll
        for (int k = 0; k < NT_; k++) s += rr[wid][t0 + k] * wts[wid][k];
        out[(size_t)row * TOUT_ + t0] = s;
    }
}

// ---------------------------------------------------------------------------
extern "C" void kernel_launch(void* const* d_in, const int* in_sizes, int n_in,
                              void* d_out, int out_size) {
    (void)in_sizes; (void)n_in; (void)out_size;
    const float* x   = (const float*)d_in[0];
    const float* wc  = (const float*)d_in[2];
    const float* wx  = (const float*)d_in[3];
    const float* wy  = (const float*)d_in[4];
    const float* wsx = (const float*)d_in[5];
    const float* wsy = (const float*)d_in[6];
    const float* wt  = (const float*)d_in[7];
    const float* wb  = (const float*)d_in[8];
    float* out = (float*)d_out;

    cudaFuncSetAttribute(gemm_kernel, cudaFuncAttributeMaxDynamicSharedMemorySize, SMEM_SZ);

    setup_kernel<<<1, N_>>>(wx, wy, wsx, wsy);
    wsfill_kernel<<<(N_ * S_ + 255) / 256, 256>>>();
    gemm_kernel<<<F_, 256, SMEM_SZ>>>(x, wc);
    conv_kernel<<<(B_ * N_) / 8, 256>>>(wt, wb, out);
}

// round 6
// speedup vs baseline: 2.1533x; 1.8583x over previous
#include <cuda_runtime.h>
#include <cuda_bf16.h>
#include <cstdint>

#define B_    4
#define C_    64
#define T_    80
#define S_    2304
#define N_    128
#define NT_   10
#define TOUT_ 71
#define F_    320
#define KC    64
#define NCHUNK 36                 // chunks per tile
#define NTILE  160                // M128 tiles
#define TOTCH  (NTILE*NCHUNK)     // 5760
#define GRID_G 148
#define NLONG  136                // CTAs with 39 chunks; rest 38

// ---------------- device scratch -------------------------------------------
__device__ __align__(16) __nv_bfloat16 g_wsT[N_*S_];    // [n][s]
__device__ float g_Rpart[NTILE*2*2*N_];                  // [tile][ord][fl][n]

// ---------------- helpers ---------------------------------------------------
__device__ __forceinline__ uint32_t smem_u32(const void* p) {
    uint32_t a;
    asm("{ .reg .u64 t; cvta.to.shared.u64 t, %1; cvt.u32.u64 %0, t; }" : "=r"(a) : "l"(p));
    return a;
}
__device__ __forceinline__ uint32_t pack_bf16(float lo, float hi) {
    uint32_t r;
    asm("cvt.rn.bf16x2.f32 %0, %1, %2;" : "=r"(r) : "f"(hi), "f"(lo));
    return r;
}
__device__ __forceinline__ void cp16(uint32_t dst, const void* src) {
    asm volatile("cp.async.cg.shared.global [%0], [%1], 16;" :: "r"(dst), "l"(src) : "memory");
}
#define CP_COMMIT() asm volatile("cp.async.commit_group;" ::: "memory")
#define CP_WAIT1()  asm volatile("cp.async.wait_group 1;" ::: "memory")

__device__ __forceinline__ void mma_bf16(float* d, const uint32_t* a, const uint32_t* b) {
    asm volatile("mma.sync.aligned.m16n8k16.row.col.f32.bf16.bf16.f32 "
        "{%0,%1,%2,%3}, {%4,%5,%6,%7}, {%8,%9}, {%0,%1,%2,%3};"
        : "+f"(d[0]), "+f"(d[1]), "+f"(d[2]), "+f"(d[3])
        : "r"(a[0]), "r"(a[1]), "r"(a[2]), "r"(a[3]), "r"(b[0]), "r"(b[1]));
}

// A: fp32 tile 128 rows x 256B, 32B granules g=0..7, XOR swizzle (R3)
__device__ __forceinline__ uint32_t aswz(int r, int g) {
    return (uint32_t)(r * 256 + (((g ^ (r & 7)) & 7) << 5));
}
// B: bf16 tile 128 rows x 128B, 16B granules (R3)
__device__ __forceinline__ uint32_t bswz(int n, int g) {
    return (uint32_t)(n * 128 + (((g ^ (n & 7)) & 7) << 4));
}

// ---------------------------------------------------------------------------
// 1) prep: blocks 0..127 -> Gaussian factors + wsT row n; blocks 128..159 zero Rpart
// ---------------------------------------------------------------------------
__global__ void prep_kernel(const float* __restrict__ wx, const float* __restrict__ wy,
                            const float* __restrict__ wsx, const float* __restrict__ wsy) {
    int blk = blockIdx.x, tid = threadIdx.x;
    if (blk < 128) {
        int n = blk;
        __shared__ float gx[64], gy[36], invz;
        if (tid < 64) {
            float rx = fmaxf(wsx[n], 0.0f);
            float inv2sx = 1.0f / (2.0f * (0.1f + rx * rx));
            float xv = ((float)tid - 32.0f + 0.5f) / 64.0f;
            float d = xv - wx[n];
            gx[tid] = expf(-d * d * inv2sx);
        } else if (tid < 100) {
            int yp = tid - 64;
            float ry = fmaxf(wsy[n], 0.0f);
            float inv2sy = 1.0f / (2.0f * (0.1f + ry * ry));
            float yv = ((float)yp - 18.0f + 0.5f) / 36.0f;
            float d = yv - wy[n];
            gy[yp] = expf(-d * d * inv2sy);
        }
        __syncthreads();
        if (tid == 0) {
            float sgx = 0.0f, sgy = 0.0f;
            for (int i = 0; i < 64; i++) sgx += gx[i];
            for (int i = 0; i < 36; i++) sgy += gy[i];
            invz = 1.0f / (0.1f + sgx * sgy);
        }
        __syncthreads();
        float iz = invz;
        for (int s = tid; s < S_; s += 256)
            g_wsT[(size_t)n * S_ + s] = __float2bfloat16(gy[s >> 6] * gx[s & 63] * iz);
    } else {
        int base = (blk - 128) * 2560;
        for (int q = tid; q < 2560; q += 256) g_Rpart[base + q] = 0.0f;
    }
}

// ---------------------------------------------------------------------------
// 2) GEMM: grid 148, each CTA owns a contiguous range of global chunk units.
//    Unit g: tile m=g/36, k-chunk k=g%36. Flush partial R at tile boundaries.
// ---------------------------------------------------------------------------
#define SM_A0   0
#define SM_A1   32768
#define SM_B0   65536
#define SM_B1   81920
#define SM_T1   98304
#define T1_STRIDE 132
#define SMEM_SZ (98304 + 128*T1_STRIDE*4)   // 165888

extern "C" __global__ void __launch_bounds__(256, 1)
gemm_kernel(const float* __restrict__ x, const float* __restrict__ wc) {
    extern __shared__ __align__(16) char smem[];
    const uint32_t sb = smem_u32(smem);
    const int tid  = threadIdx.x;
    const int wid  = tid >> 5;
    const int lane = tid & 31;
    const int wm   = wid & 3;
    const int wn   = wid >> 2;
    const int lrow = lane >> 2;
    const int lq   = lane & 3;
    const int lr   = tid >> 1;
    const int lh   = tid & 1;

    const int bi = blockIdx.x;
    const int s  = (bi < NLONG) ? 39 * bi : 39 * NLONG + 38 * (bi - NLONG);
    const int e  = s + ((bi < NLONG) ? 39 : 38);

    const uint32_t abuf[2] = { sb + SM_A0, sb + SM_A1 };
    const uint32_t bbuf[2] = { sb + SM_B0, sb + SM_B1 };

    auto issue = [&](int g, int p) {
        int m = g / NCHUNK;
        int k = g - m * NCHUNK;
        int gr = m * 128 + lr;
        int f  = gr >> 6;
        int c  = gr & 63;
        int bb = f / T_;
        int tt = f - bb * T_;
        const float* as = x + ((size_t)((bb * C_ + c) * T_ + tt)) * S_ + k * KC + lh * 32;
#pragma unroll
        for (int jj = 0; jj < 4; jj++) {
            uint32_t d = abuf[p] + aswz(lr, lh * 4 + jj);
            cp16(d,      as + jj * 8);
            cp16(d + 16, as + jj * 8 + 4);
        }
        const __nv_bfloat16* bs = g_wsT + (size_t)lr * S_ + k * KC + lh * 32;
#pragma unroll
        for (int jj = 0; jj < 4; jj++)
            cp16(bbuf[p] + bswz(lr, lh * 4 + jj), bs + jj * 8);
    };

    float acc[2][8][4];
#pragma unroll
    for (int mt = 0; mt < 2; mt++)
#pragma unroll
        for (int j = 0; j < 8; j++)
#pragma unroll
            for (int q = 0; q < 4; q++) acc[mt][j][q] = 0.0f;

    issue(s, 0);     CP_COMMIT();
    issue(s + 1, 1); CP_COMMIT();

    float* Tsm = (float*)(smem + SM_T1);

    for (int g = s; g < e; g++) {
        const int p = (g - s) & 1;
        CP_WAIT1();
        __syncthreads();
        const uint32_t Ab = abuf[p], Bb = bbuf[p];
#pragma unroll
        for (int q = 0; q < 4; q++) {
            uint32_t afr[2][4];
#pragma unroll
            for (int mt = 0; mt < 2; mt++) {
#pragma unroll
                for (int half = 0; half < 2; half++) {
#pragma unroll
                    for (int dr = 0; dr < 2; dr++) {
                        float2 v;
                        uint32_t ad = Ab + aswz(wm * 32 + mt * 16 + lrow + dr * 8,
                                                q * 2 + half) + lq * 8;
                        asm volatile("ld.shared.v2.f32 {%0,%1}, [%2];"
                                     : "=f"(v.x), "=f"(v.y) : "r"(ad));
                        afr[mt][half * 2 + dr] = pack_bf16(v.x, v.y);
                    }
                }
            }
            uint32_t bfr[8][2];
#pragma unroll
            for (int j = 0; j < 8; j++) {
                int n = wn * 64 + j * 8 + lrow;
#pragma unroll
                for (int half = 0; half < 2; half++) {
                    asm volatile("ld.shared.b32 %0, [%1];"
                        : "=r"(bfr[j][half]) : "r"(Bb + bswz(n, q * 2 + half) + lq * 4));
                }
            }
#pragma unroll
            for (int mt = 0; mt < 2; mt++)
#pragma unroll
                for (int j = 0; j < 8; j++)
                    mma_bf16(acc[mt][j], afr[mt], bfr[j]);
        }
        __syncthreads();
        if (g + 2 < e) issue(g + 2, p);
        CP_COMMIT();

        // ---- tile boundary or range end: flush partial R ----
        if ((g + 1 == e) || ((g + 1) % NCHUNK == 0)) {
            int m = g / NCHUNK;
            __syncthreads();
#pragma unroll
            for (int mt = 0; mt < 2; mt++) {
#pragma unroll
                for (int j = 0; j < 8; j++) {
                    int r0  = wm * 32 + mt * 16 + lrow;
                    int col = wn * 64 + j * 8 + lq * 2;
                    uint32_t a0 = sb + SM_T1 + (uint32_t)((r0 * T1_STRIDE + col) * 4);
                    uint32_t a1 = sb + SM_T1 + (uint32_t)(((r0 + 8) * T1_STRIDE + col) * 4);
                    asm volatile("st.shared.v2.f32 [%0], {%1,%2};"
                                 :: "r"(a0), "f"(acc[mt][j][0]), "f"(acc[mt][j][1]));
                    asm volatile("st.shared.v2.f32 [%0], {%1,%2};"
                                 :: "r"(a1), "f"(acc[mt][j][2]), "f"(acc[mt][j][3]));
                }
            }
            __syncthreads();
            {
                int fl = tid >> 7;
                int n  = tid & 127;
                float sum = 0.0f;
#pragma unroll 16
                for (int c2 = 0; c2 < 64; c2++)
                    sum += Tsm[(fl * 64 + c2) * T1_STRIDE + n] * __ldg(&wc[c2 * N_ + n]);
                int ord = (s > m * NCHUNK) ? 1 : 0;
                g_Rpart[m * 512 + ord * 256 + fl * 128 + n] = sum;
            }
#pragma unroll
            for (int mt = 0; mt < 2; mt++)
#pragma unroll
                for (int j = 0; j < 8; j++)
#pragma unroll
                    for (int q = 0; q < 4; q++) acc[mt][j][q] = 0.0f;
        }
    }
}

// ---------------------------------------------------------------------------
// 3) temporal conv: one warp per (b, n) row; R[f] = Rpart[f>>1][0|1][f&1][n]
// ---------------------------------------------------------------------------
__global__ void conv_kernel(const float* __restrict__ wt, const float* __restrict__ wb,
                            float* __restrict__ out) {
    __shared__ float rr[8][80];
    __shared__ float wts[8][10];
    int wid = threadIdx.x >> 5, lane = threadIdx.x & 31;
    int row = blockIdx.x * 8 + wid;        // row = b*N + n
    int b = row >> 7, n = row & 127;
    if (lane < 10) wts[wid][lane] = wt[lane * N_ + n];
#pragma unroll
    for (int t0 = lane; t0 < T_; t0 += 32) {
        int f = b * T_ + t0;
        int m = f >> 1, fl = f & 1;
        rr[wid][t0] = g_Rpart[m * 512 + fl * 128 + n]
                    + g_Rpart[m * 512 + 256 + fl * 128 + n];
    }
    __syncwarp();
    float bias = wb[n];
    for (int t0 = lane; t0 < TOUT_; t0 += 32) {
        float sum = bias;
#pragma unroll
        for (int k = 0; k < NT_; k++) sum += rr[wid][t0 + k] * wts[wid][k];
        out[(size_t)row * TOUT_ + t0] = sum;
    }
}

// ---------------------------------------------------------------------------
extern "C" void kernel_launch(void* const* d_in, const int* in_sizes, int n_in,
                              void* d_out, int out_size) {
    (void)in_sizes; (void)n_in; (void)out_size;
    const float* x   = (const float*)d_in[0];
    const float* wc  = (const float*)d_in[2];
    const float* wx  = (const float*)d_in[3];
    const float* wy  = (const float*)d_in[4];
    const float* wsx = (const float*)d_in[5];
    const float* wsy = (const float*)d_in[6];
    const float* wt  = (const float*)d_in[7];
    const float* wb  = (const float*)d_in[8];
    float* out = (float*)d_out;

    cudaFuncSetAttribute(gemm_kernel, cudaFuncAttributeMaxDynamicSharedMemorySize, SMEM_SZ);

    prep_kernel<<<160, 256>>>(wx, wy, wsx, wsy);
    gemm_kernel<<<GRID_G, 256, SMEM_SZ>>>(x, wc);
    conv_kernel<<<(B_ * N_) / 8, 256>>>(wt, wb, out);
}